// round 15
// baseline (speedup 1.0000x reference)
#include <cuda_runtime.h>
#include <cuda_bf16.h>
#include <math.h>
#include <stdint.h>

#define VOCAB 100000
#define EMB   300
#define HID   256
#define BATCH 64
#define SEQ   512
#define NROWS (SEQ*BATCH)   /* 32768 */
#define GCOLS 2048          /* 2 dirs * 4 gates * 256 */
#define K3MAX 1536          /* max concatenated K (layer 1: 3*512) */

// ---------------- static scratch (no allocations allowed) -------------------
__device__ float d_G [(size_t)NROWS * GCOLS];     // gate preactivations
__device__ float d_Y1[(size_t)NROWS * 512];       // layer-1 output (t,b,2H)
__device__ __nv_bfloat16 d_A2[(size_t)NROWS * K3MAX];  // [Ahi|Alo|Ahi]
__device__ __nv_bfloat16 d_W2[(size_t)GCOLS * K3MAX];  // [Whi|Whi|Wlo]

__device__ __forceinline__ float fsigm(float x) {
    return __fdividef(1.f, 1.f + __expf(-x));
}
__device__ __forceinline__ float ftanh(float x) {
    return __fdividef(2.f, 1.f + __expf(-2.f * x)) - 1.f;
}

// ---------------- MMA helpers -----------------------------------------------
__device__ __forceinline__ void ldsm_x4(uint32_t& r0, uint32_t& r1,
                                        uint32_t& r2, uint32_t& r3, uint32_t a) {
    asm volatile("ldmatrix.sync.aligned.m8n8.x4.shared.b16 {%0,%1,%2,%3}, [%4];"
                 : "=r"(r0), "=r"(r1), "=r"(r2), "=r"(r3) : "r"(a));
}
__device__ __forceinline__ void ldsm_x2(uint32_t& r0, uint32_t& r1, uint32_t a) {
    asm volatile("ldmatrix.sync.aligned.m8n8.x2.shared.b16 {%0,%1}, [%2];"
                 : "=r"(r0), "=r"(r1) : "r"(a));
}
__device__ __forceinline__ void mma16816(float* d, const uint32_t* a, const uint32_t* b) {
    asm volatile("mma.sync.aligned.m16n8k16.row.col.f32.bf16.bf16.f32 "
                 "{%0,%1,%2,%3}, {%4,%5,%6,%7}, {%8,%9}, {%0,%1,%2,%3};"
                 : "+f"(d[0]), "+f"(d[1]), "+f"(d[2]), "+f"(d[3])
                 : "r"(a[0]), "r"(a[1]), "r"(a[2]), "r"(a[3]), "r"(b[0]), "r"(b[1]));
}

// ============================================================================
// conv_a / conv_w (frozen)
// ============================================================================
__global__ void conv_a(const float* __restrict__ emb, const int* __restrict__ tokens)
{
    int r = blockIdx.x;
    int b = r & 63, t = r >> 6;
    const float* src = emb + (size_t)tokens[b * SEQ + t] * EMB;
    __nv_bfloat16* row = d_A2 + (size_t)r * 960;
    for (int c = threadIdx.x; c < 320; c += blockDim.x) {
        float x = (c < EMB) ? src[c] : 0.f;
        __nv_bfloat16 h = __float2bfloat16(x);
        row[c]       = h;
        row[320 + c] = __float2bfloat16(x - __bfloat162float(h));
        row[640 + c] = h;
    }
}

__global__ void conv_w(const float* __restrict__ w, int layer)
{
    int r = blockIdx.x;
    int K, Kp, stride;
    if (layer == 0) { K = 300; Kp = 320; stride = 960; }
    else            { K = 512; Kp = 512; stride = 1536; }
    const float* src = w + (size_t)r * K;
    __nv_bfloat16* row = d_W2 + (size_t)r * stride;
    for (int c = threadIdx.x; c < Kp; c += blockDim.x) {
        float x = (c < K) ? src[c] : 0.f;
        __nv_bfloat16 h = __float2bfloat16(x);
        row[c]        = h;
        row[Kp + c]   = h;
        row[2*Kp + c] = __float2bfloat16(x - __bfloat162float(h));
    }
}

// ============================================================================
// HMMA GEMM with 3-stage cp.async pipeline (frozen).
// ============================================================================
#define SROW 40
#define STG_B (128 * SROW * 2)
#define B_OFF (3 * STG_B)
#define BSUM_OFF (6 * STG_B)
#define GEMM_SMEM (BSUM_OFF + 512)

__device__ __forceinline__ void cpasync16(uint32_t saddr, const void* gaddr) {
    asm volatile("cp.async.cg.shared.global [%0], [%1], 16;" :: "r"(saddr), "l"(gaddr));
}
#define CP_COMMIT() asm volatile("cp.async.commit_group;" ::: "memory")
#define CP_WAIT1()  asm volatile("cp.async.wait_group 1;" ::: "memory")

__global__ void __launch_bounds__(256)
hmma_gemm(const float* __restrict__ b1, const float* __restrict__ b2, int Kp3)
{
    extern __shared__ __align__(16) char smem[];
    uint32_t sbase = (uint32_t)__cvta_generic_to_shared(smem);
    float* bsum = (float*)(smem + BSUM_OFF);

    const int tid = threadIdx.x, lane = tid & 31, w = tid >> 5;
    const int bn = blockIdx.x, bm = blockIdx.y;
    const int wm = (w & 1) * 64, wn = (w >> 1) * 32;

    if (tid < 128) { int c = bn * 128 + tid; bsum[tid] = b1[c] + b2[c]; }

    const __nv_bfloat16* gA = d_A2 + (size_t)(bm * 128) * Kp3;
    const __nv_bfloat16* gB = d_W2 + (size_t)(bn * 128) * Kp3;

    const int ar0 = tid >> 2,          ac0 = (tid & 3) * 8;
    const int ar1 = (tid + 256) >> 2,  ac1 = (tid & 3) * 8;

    float acc[4][4][4];
#pragma unroll
    for (int m = 0; m < 4; m++)
#pragma unroll
        for (int n = 0; n < 4; n++)
#pragma unroll
            for (int q = 0; q < 4; q++) acc[m][n][q] = 0.f;

    const int nk = Kp3 / 32;

    auto issue = [&](int s, int kb) {
        uint32_t sa = sbase + s * STG_B;
        uint32_t sb = sbase + B_OFF + s * STG_B;
        cpasync16(sa + (ar0 * SROW + ac0) * 2, gA + (size_t)ar0 * Kp3 + kb + ac0);
        cpasync16(sa + (ar1 * SROW + ac1) * 2, gA + (size_t)ar1 * Kp3 + kb + ac1);
        cpasync16(sb + (ar0 * SROW + ac0) * 2, gB + (size_t)ar0 * Kp3 + kb + ac0);
        cpasync16(sb + (ar1 * SROW + ac1) * 2, gB + (size_t)ar1 * Kp3 + kb + ac1);
    };

    issue(0, 0);  CP_COMMIT();
    issue(1, 32); CP_COMMIT();

    int stage = 0;
    for (int kt = 0; kt < nk; kt++) {
        CP_WAIT1();
        __syncthreads();
        if (kt + 2 < nk) issue((stage + 2) % 3, (kt + 2) * 32);
        CP_COMMIT();

        const uint32_t bA = sbase + stage * STG_B;
        const uint32_t bB = sbase + B_OFF + stage * STG_B;
#pragma unroll
        for (int ks = 0; ks < 2; ks++) {
            const int k0 = ks * 16;
            uint32_t a[4][4], bf[4][2];
#pragma unroll
            for (int mt = 0; mt < 4; mt++) {
                uint32_t ad = bA + (((wm + mt*16 + (lane & 15)) * SROW
                                     + k0 + (lane >> 4) * 8) << 1);
                ldsm_x4(a[mt][0], a[mt][1], a[mt][2], a[mt][3], ad);
            }
#pragma unroll
            for (int nt = 0; nt < 4; nt++) {
                uint32_t ad = bB + (((wn + nt*8 + (lane & 7)) * SROW
                                     + k0 + ((lane >> 3) & 1) * 8) << 1);
                ldsm_x2(bf[nt][0], bf[nt][1], ad);
            }
#pragma unroll
            for (int mt = 0; mt < 4; mt++)
#pragma unroll
                for (int nt = 0; nt < 4; nt++)
                    mma16816(acc[mt][nt], a[mt], bf[nt]);
        }
        stage = (stage + 1) % 3;
    }

#pragma unroll
    for (int mt = 0; mt < 4; mt++) {
        int r0 = bm * 128 + wm + mt * 16 + (lane >> 2);
#pragma unroll
        for (int nt = 0; nt < 4; nt++) {
            int c  = wn + nt * 8 + (lane & 3) * 2;
            int cg = bn * 128 + c;
            float2 v0 = make_float2(acc[mt][nt][0] + bsum[c],
                                    acc[mt][nt][1] + bsum[c + 1]);
            float2 v1 = make_float2(acc[mt][nt][2] + bsum[c],
                                    acc[mt][nt][3] + bsum[c + 1]);
            *(float2*)&d_G[(size_t)r0 * GCOLS + cg]       = v0;
            *(float2*)&d_G[(size_t)(r0 + 8) * GCOLS + cg] = v1;
        }
    }
}

// ============================================================================
// LSTM recurrence v6: interleaved dirs, 4-batch chunks (16 clusters, 128 CTAs),
// push exchange (halved), fused hi/lo h-fragment ldsm_x4.
// SMEM: [Wlo d0][Wlo d1][SCRATCH: Hd[2d][2par][2pl][8][264] | ps | mbar]
//   (batch rows 4..7 of H are permanently zero — mma N-padding)
// ============================================================================
#define HSTR 264
#define WLO0 0
#define WLO1 67584
#define SCR  135168
#define HBUF 8448                       /* per (dir,par): 2 planes x 8 x 264 x 2B */
#define LOB2 4224                       /* hi->lo plane offset */
#define PS_OFF (SCR + 33792)
#define MB_OFF (PS_OFF + 4352)
#define LSTM_SMEM (SCR + 67584)         /* 202752 */

__device__ __forceinline__ void mbar_wait_cluster(uint32_t mb, uint32_t parity) {
    uint32_t done;
    asm volatile("{\n\t.reg .pred p;\n\t"
                 "mbarrier.try_wait.parity.acquire.cluster.shared::cta.b64 p, [%1], %2;\n\t"
                 "selp.b32 %0, 1, 0, p;\n\t}"
                 : "=r"(done) : "r"(mb), "r"(parity) : "memory");
    if (!done) {
        asm volatile("{\n\t.reg .pred P1;\n\t"
                     "WL_%=:\n\t"
                     "mbarrier.try_wait.parity.acquire.cluster.shared::cta.b64 P1, [%0], %1, 0x989680;\n\t"
                     "@P1 bra.uni WD_%=;\n\t"
                     "bra.uni WL_%=;\n\t"
                     "WD_%=:\n\t}" :: "r"(mb), "r"(parity) : "memory");
    }
}

__global__ void __cluster_dims__(8,1,1) __launch_bounds__(256,1)
lstm_rec(const float* __restrict__ whh, int layer)
{
    extern __shared__ __align__(16) char ls[];
    uint32_t smb = (uint32_t)__cvta_generic_to_shared(ls);
    float* ps = (float*)(ls + PS_OFF);

    const int tid  = threadIdx.x;
    const int lane = tid & 31;
    const int w    = tid >> 5;          // warp = m-tile; batches 0..3 on w<4
    const int hc   = blockIdx.x & 7;    // cluster rank = col stripe
    const int B0   = (blockIdx.x >> 3) * 4;   // 16 chunks of 4 batches

    // ---- prologue: per dir, split W; Whi->SCRATCH (frag preload), Wlo->resident
    uint32_t wh[2][16][4];
#pragma unroll
    for (int d = 0; d < 2; d++) {
        __nv_bfloat16* WhiT = (__nv_bfloat16*)(ls + SCR);
        __nv_bfloat16* WloR = (__nv_bfloat16*)(ls + (d ? WLO1 : WLO0));
        for (int idx = tid; idx < 128 * 256; idx += 256) {
            int r = idx >> 8, k = idx & 255;
            float x = whh[((size_t)d*1024 + (r>>5)*256 + hc*32 + (r&31)) * 256 + k];
            __nv_bfloat16 hi = __float2bfloat16(x);
            WhiT[r*HSTR + k] = hi;
            WloR[r*HSTR + k] = __float2bfloat16(x - __bfloat162float(hi));
        }
        __syncthreads();
#pragma unroll
        for (int ks = 0; ks < 16; ks++) {
            uint32_t ao = (((w*16 + (lane & 15)) * HSTR + ks*16 + (lane >> 4)*8) << 1);
            ldsm_x4(wh[d][ks][0], wh[d][ks][1], wh[d][ks][2], wh[d][ks][3],
                    smb + SCR + ao);
        }
        __syncthreads();
    }

    // ---- zero Hd (overwrites Whi staging), init mbars (count 8x256=2048) ----
    for (int i = tid; i < 33792/4; i += 256) ((uint32_t*)(ls + SCR))[i] = 0u;
    if (tid == 0) {
        asm volatile("mbarrier.init.shared.b64 [%0], %1;" :: "r"(smb + MB_OFF),     "r"(2048u) : "memory");
        asm volatile("mbarrier.init.shared.b64 [%0], %1;" :: "r"(smb + MB_OFF + 8), "r"(2048u) : "memory");
    }
    __syncthreads();
    asm volatile("barrier.cluster.arrive.aligned;" ::: "memory");
    asm volatile("barrier.cluster.wait.aligned;"   ::: "memory");

    // precompute mapped push addresses (own slot in each peer CTA, buffer 0)
    uint32_t pa[8];
    if (w < 4) {
        uint32_t own = smb + SCR + (uint32_t)((w*HSTR + hc*32 + lane) << 1);
#pragma unroll
        for (unsigned r = 0; r < 8; r++)
            asm volatile("mapa.shared::cluster.u32 %0, %1, %2;"
                         : "=r"(pa[r]) : "r"(own), "r"(r));
    }
    uint32_t mbmap[2];   // mapped mbar addr for elected arrive (rank = tid)
    if (tid < 8) {
        asm volatile("mapa.shared::cluster.u32 %0, %1, %2;"
                     : "=r"(mbmap[0]) : "r"(smb + MB_OFF),     "r"(tid));
        asm volatile("mapa.shared::cluster.u32 %0, %1, %2;"
                     : "=r"(mbmap[1]) : "r"(smb + MB_OFF + 8), "r"(tid));
    }

    float creg[2] = {0.f, 0.f};

    for (int t = 0; t < SEQ; t++) {
        const int par = t & 1;
        // prefetch gate preactivations for BOTH dirs before any wait (w<4 only)
        float gp[2][4];
        if (w < 4) {
            size_t rowb = ((size_t)t*64 + B0 + w) * GCOLS;
#pragma unroll
            for (int d = 0; d < 2; d++)
#pragma unroll
                for (int g = 0; g < 4; g++)
                    gp[d][g] = d_G[rowb + (size_t)d*1024 + g*256 + hc*32 + lane];
        }

#pragma unroll
        for (int d = 0; d < 2; d++) {
            const uint32_t Hp = smb + SCR + (uint32_t)((d*2 + par) * HBUF);
            const uint32_t mb = smb + MB_OFF + d*8;

            if (t > 0) mbar_wait_cluster(mb, (uint32_t)((t + 1) & 1));

            // ---- tensor dot: D[128x8] = Whi.hhi + Whi.hlo + Wlo.hhi ----
            float aA[2][4], aB[2][4], aC[2][4];
#pragma unroll
            for (int q = 0; q < 4; q++) {
                aA[0][q] = aA[1][q] = 0.f;
                aB[0][q] = aB[1][q] = 0.f;
                aC[0][q] = aC[1][q] = 0.f;
            }
            // fused hi/lo B-fragment: lanes 0-7 hi/k0, 8-15 hi/k8, 16-23 lo/k0, 24-31 lo/k8
            const uint32_t hb = Hp
                + (uint32_t)((((lane >> 4) & 1) * LOB2)
                + ((((lane & 7) * HSTR) + (((lane >> 3) & 1) * 8)) << 1));
            const uint32_t wlo = smb + (d ? WLO1 : WLO0);
#pragma unroll
            for (int ks = 0; ks < 16; ks++) {
                uint32_t hf[4], wl[4];
                ldsm_x4(hf[0], hf[1], hf[2], hf[3], hb + (uint32_t)(ks * 32));
                uint32_t ao = (((w*16 + (lane & 15)) * HSTR + ks*16 + (lane >> 4)*8) << 1);
                ldsm_x4(wl[0], wl[1], wl[2], wl[3], wlo + ao);
                mma16816(aA[ks & 1], wh[d][ks], hf);       // Whi . hhi
                mma16816(aB[ks & 1], wh[d][ks], hf + 2);   // Whi . hlo
                mma16816(aC[ks & 1], wl, hf);              // Wlo . hhi
            }
            // transpose through ps
            {
                int gr = w*16 + (lane >> 2);
                int c0 = (lane & 3) * 2;
                float v0 = aA[0][0]+aA[1][0]+aB[0][0]+aB[1][0]+aC[0][0]+aC[1][0];
                float v1 = aA[0][1]+aA[1][1]+aB[0][1]+aB[1][1]+aC[0][1]+aC[1][1];
                float v2 = aA[0][2]+aA[1][2]+aB[0][2]+aB[1][2]+aC[0][2]+aC[1][2];
                float v3 = aA[0][3]+aA[1][3]+aB[0][3]+aB[1][3]+aC[0][3]+aC[1][3];
                ps[c0*136 + gr]         = v0;
                ps[(c0+1)*136 + gr]     = v1;
                ps[c0*136 + gr + 8]     = v2;
                ps[(c0+1)*136 + gr + 8] = v3;
            }
            __syncthreads();

            // ---- cell update + push (batches 0..3 on warps 0..3) ----
            if (w < 4) {
                float si = ps[w*136 + lane]      + gp[d][0];
                float sf = ps[w*136 + 32 + lane] + gp[d][1];
                float sg = ps[w*136 + 64 + lane] + gp[d][2];
                float so = ps[w*136 + 96 + lane] + gp[d][3];
                float iv = fsigm(si);
                float fv = fsigm(sf);
                float ov = fsigm(so);
                creg[d] = fv * creg[d] + iv * ftanh(sg);
                float hnew = ov * ftanh(creg[d]);

                __nv_bfloat16 hh = __float2bfloat16(hnew);
                __nv_bfloat16 hl = __float2bfloat16(hnew - __bfloat162float(hh));
                unsigned short hb16 = __bfloat16_as_ushort(hh);
                unsigned short lb16 = __bfloat16_as_ushort(hl);

                // PUSH (hi,lo) into next-parity buffer of ALL 8 CTAs
                uint32_t off = (uint32_t)((d*2 + (par^1)) * HBUF);
#pragma unroll
                for (unsigned r = 0; r < 8; r++) {
                    asm volatile("st.shared::cluster.u16 [%0], %1;"
                                 :: "r"(pa[r] + off), "h"(hb16) : "memory");
                    asm volatile("st.shared::cluster.u16 [%0], %1;"
                                 :: "r"(pa[r] + off + LOB2), "h"(lb16) : "memory");
                }

                // global h store (off critical path)
                int col = d*256 + hc*32 + lane;
                size_t orow = (size_t)t*64 + B0 + w;
                if (layer == 0) {
                    __nv_bfloat16* arow = d_A2 + orow * 1536;
                    arow[col]        = hh;
                    arow[512 + col]  = hl;
                    arow[1024 + col] = hh;
                } else {
                    d_Y1[orow * 512 + col] = hnew;
                }
            }
            __syncthreads();

            // ---- elected remote arrives (count 256 each) ----
            if (tid < 8)
                asm volatile("mbarrier.arrive.release.cluster.shared::cluster.b64 _, [%0], %1;"
                             :: "r"(mbmap[d]), "r"(256u) : "memory");
        }
    }

    asm volatile("barrier.cluster.arrive.aligned;" ::: "memory");
    asm volatile("barrier.cluster.wait.aligned;"   ::: "memory");
}

// ============================================================================
// Epilogue (frozen)
// ============================================================================
__global__ void __launch_bounds__(512)
epilogue(const int* __restrict__ pos, const float* __restrict__ wcls,
         const float* __restrict__ bcls, float* __restrict__ out)
{
    __shared__ float s0[512], s1[512];
    int b = blockIdx.x, i = threadIdx.x;
    int t = pos[b];
    float y = d_Y1[((size_t)t*64 + b) * 512 + i];
    out[256 + b*512 + i] = y;
    s0[i] = y * wcls[i];
    s1[i] = y * wcls[512 + i];
    __syncthreads();
    for (int st = 256; st > 0; st >>= 1) {
        if (i < st) { s0[i] += s0[i+st]; s1[i] += s1[i+st]; }
        __syncthreads();
    }
    if (i == 0) {
        float l0 = s0[0] + bcls[0], l1 = s1[0] + bcls[1];
        out[b*2+0] = l0;            out[b*2+1] = l1;
        out[128 + b*2+0] = 1.f/(1.f+expf(-l0));
        out[128 + b*2+1] = 1.f/(1.f+expf(-l1));
    }
}

// ============================================================================
extern "C" void kernel_launch(void* const* d_in, const int* in_sizes, int n_in,
                              void* d_out, int out_size)
{
    const float *emb=0,*wih0=0,*whh0=0,*bih0=0,*bhh0=0;
    const float *wih1=0,*whh1=0,*bih1=0,*bhh1=0,*wcls=0,*bcls=0;
    const int *ctx=0,*pos=0;
    int nwhh = 0, nb = 0;
    for (int i = 0; i < n_in; i++) {
        int s = in_sizes[i]; const void* p = d_in[i];
        switch (s) {
            case 30000000: emb  = (const float*)p; break;
            case 614400:   wih0 = (const float*)p; break;
            case 1048576:  wih1 = (const float*)p; break;
            case 524288:   if (nwhh++ == 0) whh0 = (const float*)p;
                           else             whh1 = (const float*)p; break;
            case 2048:     if (nb == 0) bih0 = (const float*)p;
                           else if (nb == 1) bhh0 = (const float*)p;
                           else if (nb == 2) bih1 = (const float*)p;
                           else              bhh1 = (const float*)p;
                           nb++; break;
            case 1024:     wcls = (const float*)p; break;
            case 2:        bcls = (const float*)p; break;
            case 32768:    ctx  = (const int*)p; break;
            case 64:       pos  = (const int*)p; break;
            default: break;
        }
    }

    cudaFuncSetAttribute(hmma_gemm, cudaFuncAttributeMaxDynamicSharedMemorySize, GEMM_SMEM);
    cudaFuncSetAttribute(lstm_rec,  cudaFuncAttributeMaxDynamicSharedMemorySize, LSTM_SMEM);

    dim3 ggrid(16, 256);
    // layer 0
    conv_a<<<NROWS, 128>>>(emb, ctx);
    conv_w<<<GCOLS, 128>>>(wih0, 0);
    hmma_gemm<<<ggrid, 256, GEMM_SMEM>>>(bih0, bhh0, 960);
    lstm_rec<<<128, 256, LSTM_SMEM>>>(whh0, 0);   // both dirs; writes d_A2
    // layer 1
    conv_w<<<GCOLS, 128>>>(wih1, 1);
    hmma_gemm<<<ggrid, 256, GEMM_SMEM>>>(bih1, bhh1, 1536);
    lstm_rec<<<128, 256, LSTM_SMEM>>>(whh1, 1);   // both dirs; writes d_Y1
    // classifier
    epilogue<<<64, 512>>>(pos, wcls, bcls, (float*)d_out);
}

// round 16
// speedup vs baseline: 1.6009x; 1.6009x over previous
#include <cuda_runtime.h>
#include <cuda_bf16.h>
#include <math.h>
#include <stdint.h>

#define VOCAB 100000
#define EMB   300
#define HID   256
#define BATCH 64
#define SEQ   512
#define NROWS (SEQ*BATCH)   /* 32768 */
#define GCOLS 2048          /* 2 dirs * 4 gates * 256 */
#define K3MAX 1536          /* max concatenated K (layer 1: 3*512) */

// ---------------- static scratch (no allocations allowed) -------------------
__device__ float d_G [(size_t)NROWS * GCOLS];     // gate preactivations
__device__ float d_Y1[(size_t)NROWS * 512];       // layer-1 output (t,b,2H)
__device__ __nv_bfloat16 d_A2[(size_t)NROWS * K3MAX];  // [Ahi|Alo|Ahi]
__device__ __nv_bfloat16 d_W2[(size_t)GCOLS * K3MAX];  // [Whi|Whi|Wlo]

__device__ __forceinline__ float fsigm(float x) {
    return __fdividef(1.f, 1.f + __expf(-x));
}
__device__ __forceinline__ float ftanh(float x) {
    return __fdividef(2.f, 1.f + __expf(-2.f * x)) - 1.f;
}

// ---------------- MMA helpers -----------------------------------------------
__device__ __forceinline__ void ldsm_x4(uint32_t& r0, uint32_t& r1,
                                        uint32_t& r2, uint32_t& r3, uint32_t a) {
    asm volatile("ldmatrix.sync.aligned.m8n8.x4.shared.b16 {%0,%1,%2,%3}, [%4];"
                 : "=r"(r0), "=r"(r1), "=r"(r2), "=r"(r3) : "r"(a));
}
__device__ __forceinline__ void ldsm_x2(uint32_t& r0, uint32_t& r1, uint32_t a) {
    asm volatile("ldmatrix.sync.aligned.m8n8.x2.shared.b16 {%0,%1}, [%2];"
                 : "=r"(r0), "=r"(r1) : "r"(a));
}
__device__ __forceinline__ void mma16816(float* d, const uint32_t* a, const uint32_t* b) {
    asm volatile("mma.sync.aligned.m16n8k16.row.col.f32.bf16.bf16.f32 "
                 "{%0,%1,%2,%3}, {%4,%5,%6,%7}, {%8,%9}, {%0,%1,%2,%3};"
                 : "+f"(d[0]), "+f"(d[1]), "+f"(d[2]), "+f"(d[3])
                 : "r"(a[0]), "r"(a[1]), "r"(a[2]), "r"(a[3]), "r"(b[0]), "r"(b[1]));
}

// ============================================================================
// conv_a / conv_w (frozen)
// ============================================================================
__global__ void conv_a(const float* __restrict__ emb, const int* __restrict__ tokens)
{
    int r = blockIdx.x;
    int b = r & 63, t = r >> 6;
    const float* src = emb + (size_t)tokens[b * SEQ + t] * EMB;
    __nv_bfloat16* row = d_A2 + (size_t)r * 960;
    for (int c = threadIdx.x; c < 320; c += blockDim.x) {
        float x = (c < EMB) ? src[c] : 0.f;
        __nv_bfloat16 h = __float2bfloat16(x);
        row[c]       = h;
        row[320 + c] = __float2bfloat16(x - __bfloat162float(h));
        row[640 + c] = h;
    }
}

__global__ void conv_w(const float* __restrict__ w, int layer)
{
    int r = blockIdx.x;
    int K, Kp, stride;
    if (layer == 0) { K = 300; Kp = 320; stride = 960; }
    else            { K = 512; Kp = 512; stride = 1536; }
    const float* src = w + (size_t)r * K;
    __nv_bfloat16* row = d_W2 + (size_t)r * stride;
    for (int c = threadIdx.x; c < Kp; c += blockDim.x) {
        float x = (c < K) ? src[c] : 0.f;
        __nv_bfloat16 h = __float2bfloat16(x);
        row[c]        = h;
        row[Kp + c]   = h;
        row[2*Kp + c] = __float2bfloat16(x - __bfloat162float(h));
    }
}

// ============================================================================
// HMMA GEMM with 3-stage cp.async pipeline (frozen).
// ============================================================================
#define SROW 40
#define STG_B (128 * SROW * 2)
#define B_OFF (3 * STG_B)
#define BSUM_OFF (6 * STG_B)
#define GEMM_SMEM (BSUM_OFF + 512)

__device__ __forceinline__ void cpasync16(uint32_t saddr, const void* gaddr) {
    asm volatile("cp.async.cg.shared.global [%0], [%1], 16;" :: "r"(saddr), "l"(gaddr));
}
#define CP_COMMIT() asm volatile("cp.async.commit_group;" ::: "memory")
#define CP_WAIT1()  asm volatile("cp.async.wait_group 1;" ::: "memory")

__global__ void __launch_bounds__(256)
hmma_gemm(const float* __restrict__ b1, const float* __restrict__ b2, int Kp3)
{
    extern __shared__ __align__(16) char smem[];
    uint32_t sbase = (uint32_t)__cvta_generic_to_shared(smem);
    float* bsum = (float*)(smem + BSUM_OFF);

    const int tid = threadIdx.x, lane = tid & 31, w = tid >> 5;
    const int bn = blockIdx.x, bm = blockIdx.y;
    const int wm = (w & 1) * 64, wn = (w >> 1) * 32;

    if (tid < 128) { int c = bn * 128 + tid; bsum[tid] = b1[c] + b2[c]; }

    const __nv_bfloat16* gA = d_A2 + (size_t)(bm * 128) * Kp3;
    const __nv_bfloat16* gB = d_W2 + (size_t)(bn * 128) * Kp3;

    const int ar0 = tid >> 2,          ac0 = (tid & 3) * 8;
    const int ar1 = (tid + 256) >> 2,  ac1 = (tid & 3) * 8;

    float acc[4][4][4];
#pragma unroll
    for (int m = 0; m < 4; m++)
#pragma unroll
        for (int n = 0; n < 4; n++)
#pragma unroll
            for (int q = 0; q < 4; q++) acc[m][n][q] = 0.f;

    const int nk = Kp3 / 32;

    auto issue = [&](int s, int kb) {
        uint32_t sa = sbase + s * STG_B;
        uint32_t sb = sbase + B_OFF + s * STG_B;
        cpasync16(sa + (ar0 * SROW + ac0) * 2, gA + (size_t)ar0 * Kp3 + kb + ac0);
        cpasync16(sa + (ar1 * SROW + ac1) * 2, gA + (size_t)ar1 * Kp3 + kb + ac1);
        cpasync16(sb + (ar0 * SROW + ac0) * 2, gB + (size_t)ar0 * Kp3 + kb + ac0);
        cpasync16(sb + (ar1 * SROW + ac1) * 2, gB + (size_t)ar1 * Kp3 + kb + ac1);
    };

    issue(0, 0);  CP_COMMIT();
    issue(1, 32); CP_COMMIT();

    int stage = 0;
    for (int kt = 0; kt < nk; kt++) {
        CP_WAIT1();
        __syncthreads();
        if (kt + 2 < nk) issue((stage + 2) % 3, (kt + 2) * 32);
        CP_COMMIT();

        const uint32_t bA = sbase + stage * STG_B;
        const uint32_t bB = sbase + B_OFF + stage * STG_B;
#pragma unroll
        for (int ks = 0; ks < 2; ks++) {
            const int k0 = ks * 16;
            uint32_t a[4][4], bf[4][2];
#pragma unroll
            for (int mt = 0; mt < 4; mt++) {
                uint32_t ad = bA + (((wm + mt*16 + (lane & 15)) * SROW
                                     + k0 + (lane >> 4) * 8) << 1);
                ldsm_x4(a[mt][0], a[mt][1], a[mt][2], a[mt][3], ad);
            }
#pragma unroll
            for (int nt = 0; nt < 4; nt++) {
                uint32_t ad = bB + (((wn + nt*8 + (lane & 7)) * SROW
                                     + k0 + ((lane >> 3) & 1) * 8) << 1);
                ldsm_x2(bf[nt][0], bf[nt][1], ad);
            }
#pragma unroll
            for (int mt = 0; mt < 4; mt++)
#pragma unroll
                for (int nt = 0; nt < 4; nt++)
                    mma16816(acc[mt][nt], a[mt], bf[nt]);
        }
        stage = (stage + 1) % 3;
    }

#pragma unroll
    for (int mt = 0; mt < 4; mt++) {
        int r0 = bm * 128 + wm + mt * 16 + (lane >> 2);
#pragma unroll
        for (int nt = 0; nt < 4; nt++) {
            int c  = wn + nt * 8 + (lane & 3) * 2;
            int cg = bn * 128 + c;
            float2 v0 = make_float2(acc[mt][nt][0] + bsum[c],
                                    acc[mt][nt][1] + bsum[c + 1]);
            float2 v1 = make_float2(acc[mt][nt][2] + bsum[c],
                                    acc[mt][nt][3] + bsum[c + 1]);
            *(float2*)&d_G[(size_t)r0 * GCOLS + cg]       = v0;
            *(float2*)&d_G[(size_t)(r0 + 8) * GCOLS + cg] = v1;
        }
    }
}

// ============================================================================
// LSTM recurrence v7 = R14 config (8 clusters x 8 CTAs, 8 batches/CTA,
// push exchange, elected arrives) + fused hi/lo h-fragment ldsm_x4.
// SMEM: [Wlo d0][Wlo d1][SCRATCH: Hd[2d][2par][2pl][8][264] | ps | mbar]
// ============================================================================
#define HSTR 264
#define WLO0 0
#define WLO1 67584
#define SCR  135168
#define HBUF 8448                       /* per (dir,par): 2 planes x 8 x 264 x 2B */
#define LOB2 4224                       /* hi->lo plane offset */
#define PS_OFF (SCR + 33792)
#define MB_OFF (PS_OFF + 4352)
#define LSTM_SMEM (SCR + 67584)         /* 202752 */

__device__ __forceinline__ void mbar_wait_cluster(uint32_t mb, uint32_t parity) {
    uint32_t done;
    asm volatile("{\n\t.reg .pred p;\n\t"
                 "mbarrier.try_wait.parity.acquire.cluster.shared::cta.b64 p, [%1], %2;\n\t"
                 "selp.b32 %0, 1, 0, p;\n\t}"
                 : "=r"(done) : "r"(mb), "r"(parity) : "memory");
    if (!done) {
        asm volatile("{\n\t.reg .pred P1;\n\t"
                     "WL_%=:\n\t"
                     "mbarrier.try_wait.parity.acquire.cluster.shared::cta.b64 P1, [%0], %1, 0x989680;\n\t"
                     "@P1 bra.uni WD_%=;\n\t"
                     "bra.uni WL_%=;\n\t"
                     "WD_%=:\n\t}" :: "r"(mb), "r"(parity) : "memory");
    }
}

__global__ void __cluster_dims__(8,1,1) __launch_bounds__(256,1)
lstm_rec(const float* __restrict__ whh, int layer)
{
    extern __shared__ __align__(16) char ls[];
    uint32_t smb = (uint32_t)__cvta_generic_to_shared(ls);
    float* ps = (float*)(ls + PS_OFF);

    const int tid  = threadIdx.x;
    const int lane = tid & 31;
    const int w    = tid >> 5;          // warp = m-tile AND update batch
    const int hc   = blockIdx.x & 7;    // cluster rank = col stripe
    const int B0   = (blockIdx.x >> 3) * 8;

    // ---- prologue: per dir, split W; Whi->SCRATCH (frag preload), Wlo->resident
    uint32_t wh[2][16][4];
#pragma unroll
    for (int d = 0; d < 2; d++) {
        __nv_bfloat16* WhiT = (__nv_bfloat16*)(ls + SCR);
        __nv_bfloat16* WloR = (__nv_bfloat16*)(ls + (d ? WLO1 : WLO0));
        for (int idx = tid; idx < 128 * 256; idx += 256) {
            int r = idx >> 8, k = idx & 255;
            float x = whh[((size_t)d*1024 + (r>>5)*256 + hc*32 + (r&31)) * 256 + k];
            __nv_bfloat16 hi = __float2bfloat16(x);
            WhiT[r*HSTR + k] = hi;
            WloR[r*HSTR + k] = __float2bfloat16(x - __bfloat162float(hi));
        }
        __syncthreads();
#pragma unroll
        for (int ks = 0; ks < 16; ks++) {
            uint32_t ao = (((w*16 + (lane & 15)) * HSTR + ks*16 + (lane >> 4)*8) << 1);
            ldsm_x4(wh[d][ks][0], wh[d][ks][1], wh[d][ks][2], wh[d][ks][3],
                    smb + SCR + ao);
        }
        __syncthreads();
    }

    // ---- zero Hd (overwrites Whi staging), init mbars (count 8x256=2048) ----
    for (int i = tid; i < 33792/4; i += 256) ((uint32_t*)(ls + SCR))[i] = 0u;
    if (tid == 0) {
        asm volatile("mbarrier.init.shared.b64 [%0], %1;" :: "r"(smb + MB_OFF),     "r"(2048u) : "memory");
        asm volatile("mbarrier.init.shared.b64 [%0], %1;" :: "r"(smb + MB_OFF + 8), "r"(2048u) : "memory");
    }
    __syncthreads();
    asm volatile("barrier.cluster.arrive.aligned;" ::: "memory");
    asm volatile("barrier.cluster.wait.aligned;"   ::: "memory");

    // precompute mapped push addresses (own slot in each peer CTA, buffer 0)
    uint32_t pa[8];
    {
        uint32_t own = smb + SCR + (uint32_t)((w*HSTR + hc*32 + lane) << 1);
#pragma unroll
        for (unsigned r = 0; r < 8; r++)
            asm volatile("mapa.shared::cluster.u32 %0, %1, %2;"
                         : "=r"(pa[r]) : "r"(own), "r"(r));
    }
    uint32_t mbmap[2];   // mapped mbar addr for elected arrive (rank = tid)
    if (tid < 8) {
        asm volatile("mapa.shared::cluster.u32 %0, %1, %2;"
                     : "=r"(mbmap[0]) : "r"(smb + MB_OFF),     "r"(tid));
        asm volatile("mapa.shared::cluster.u32 %0, %1, %2;"
                     : "=r"(mbmap[1]) : "r"(smb + MB_OFF + 8), "r"(tid));
    }

    float creg[2] = {0.f, 0.f};

    for (int t = 0; t < SEQ; t++) {
        const int par = t & 1;
        // prefetch gate preactivations for BOTH dirs before any wait
        float gp[2][4];
        size_t rowb = ((size_t)t*64 + B0 + w) * GCOLS;
#pragma unroll
        for (int d = 0; d < 2; d++)
#pragma unroll
            for (int g = 0; g < 4; g++)
                gp[d][g] = d_G[rowb + (size_t)d*1024 + g*256 + hc*32 + lane];

#pragma unroll
        for (int d = 0; d < 2; d++) {
            const uint32_t Hp = smb + SCR + (uint32_t)((d*2 + par) * HBUF);
            const uint32_t mb = smb + MB_OFF + d*8;

            if (t > 0) mbar_wait_cluster(mb, (uint32_t)((t + 1) & 1));

            // ---- tensor dot: D[128x8] = Whi.hhi + Whi.hlo + Wlo.hhi ----
            float aA[2][4], aB[2][4], aC[2][4];
#pragma unroll
            for (int q = 0; q < 4; q++) {
                aA[0][q] = aA[1][q] = 0.f;
                aB[0][q] = aB[1][q] = 0.f;
                aC[0][q] = aC[1][q] = 0.f;
            }
            // fused hi/lo B-fragment: lanes 0-7 hi/k0, 8-15 hi/k8, 16-23 lo/k0, 24-31 lo/k8
            const uint32_t hb = Hp
                + (uint32_t)((((lane >> 4) & 1) * LOB2)
                + ((((lane & 7) * HSTR) + (((lane >> 3) & 1) * 8)) << 1));
            const uint32_t wlo = smb + (d ? WLO1 : WLO0);
#pragma unroll
            for (int ks = 0; ks < 16; ks++) {
                uint32_t hf[4], wl[4];
                ldsm_x4(hf[0], hf[1], hf[2], hf[3], hb + (uint32_t)(ks * 32));
                uint32_t ao = (((w*16 + (lane & 15)) * HSTR + ks*16 + (lane >> 4)*8) << 1);
                ldsm_x4(wl[0], wl[1], wl[2], wl[3], wlo + ao);
                mma16816(aA[ks & 1], wh[d][ks], hf);       // Whi . hhi
                mma16816(aB[ks & 1], wh[d][ks], hf + 2);   // Whi . hlo
                mma16816(aC[ks & 1], wl, hf);              // Wlo . hhi
            }
            // transpose through ps
            {
                int gr = w*16 + (lane >> 2);
                int c0 = (lane & 3) * 2;
                float v0 = aA[0][0]+aA[1][0]+aB[0][0]+aB[1][0]+aC[0][0]+aC[1][0];
                float v1 = aA[0][1]+aA[1][1]+aB[0][1]+aB[1][1]+aC[0][1]+aC[1][1];
                float v2 = aA[0][2]+aA[1][2]+aB[0][2]+aB[1][2]+aC[0][2]+aC[1][2];
                float v3 = aA[0][3]+aA[1][3]+aB[0][3]+aB[1][3]+aC[0][3]+aC[1][3];
                ps[c0*136 + gr]         = v0;
                ps[(c0+1)*136 + gr]     = v1;
                ps[c0*136 + gr + 8]     = v2;
                ps[(c0+1)*136 + gr + 8] = v3;
            }
            __syncthreads();

            // ---- cell update (batch=w, col=lane within stripe) ----
            float si = ps[w*136 + lane]      + gp[d][0];
            float sf = ps[w*136 + 32 + lane] + gp[d][1];
            float sg = ps[w*136 + 64 + lane] + gp[d][2];
            float so = ps[w*136 + 96 + lane] + gp[d][3];
            float iv = fsigm(si);
            float fv = fsigm(sf);
            float ov = fsigm(so);
            creg[d] = fv * creg[d] + iv * ftanh(sg);
            float hnew = ov * ftanh(creg[d]);

            __nv_bfloat16 hh = __float2bfloat16(hnew);
            __nv_bfloat16 hl = __float2bfloat16(hnew - __bfloat162float(hh));
            unsigned short hb16 = __bfloat16_as_ushort(hh);
            unsigned short lb16 = __bfloat16_as_ushort(hl);

            // ---- PUSH (hi,lo) into next-parity buffer of ALL 8 CTAs ----
            uint32_t off = (uint32_t)((d*2 + (par^1)) * HBUF);
#pragma unroll
            for (unsigned r = 0; r < 8; r++) {
                asm volatile("st.shared::cluster.u16 [%0], %1;"
                             :: "r"(pa[r] + off), "h"(hb16) : "memory");
                asm volatile("st.shared::cluster.u16 [%0], %1;"
                             :: "r"(pa[r] + off + LOB2), "h"(lb16) : "memory");
            }
            __syncthreads();

            // ---- elected remote arrives (count 256 each) ----
            if (tid < 8)
                asm volatile("mbarrier.arrive.release.cluster.shared::cluster.b64 _, [%0], %1;"
                             :: "r"(mbmap[d]), "r"(256u) : "memory");

            // ---- global h store (off critical path) ----
            int col = d*256 + hc*32 + lane;
            size_t orow = (size_t)t*64 + B0 + w;
            if (layer == 0) {
                __nv_bfloat16* arow = d_A2 + orow * 1536;
                arow[col]        = hh;
                arow[512 + col]  = hl;
                arow[1024 + col] = hh;
            } else {
                d_Y1[orow * 512 + col] = hnew;
            }
        }
    }

    asm volatile("barrier.cluster.arrive.aligned;" ::: "memory");
    asm volatile("barrier.cluster.wait.aligned;"   ::: "memory");
}

// ============================================================================
// Epilogue (frozen)
// ============================================================================
__global__ void __launch_bounds__(512)
epilogue(const int* __restrict__ pos, const float* __restrict__ wcls,
         const float* __restrict__ bcls, float* __restrict__ out)
{
    __shared__ float s0[512], s1[512];
    int b = blockIdx.x, i = threadIdx.x;
    int t = pos[b];
    float y = d_Y1[((size_t)t*64 + b) * 512 + i];
    out[256 + b*512 + i] = y;
    s0[i] = y * wcls[i];
    s1[i] = y * wcls[512 + i];
    __syncthreads();
    for (int st = 256; st > 0; st >>= 1) {
        if (i < st) { s0[i] += s0[i+st]; s1[i] += s1[i+st]; }
        __syncthreads();
    }
    if (i == 0) {
        float l0 = s0[0] + bcls[0], l1 = s1[0] + bcls[1];
        out[b*2+0] = l0;            out[b*2+1] = l1;
        out[128 + b*2+0] = 1.f/(1.f+expf(-l0));
        out[128 + b*2+1] = 1.f/(1.f+expf(-l1));
    }
}

// ============================================================================
extern "C" void kernel_launch(void* const* d_in, const int* in_sizes, int n_in,
                              void* d_out, int out_size)
{
    const float *emb=0,*wih0=0,*whh0=0,*bih0=0,*bhh0=0;
    const float *wih1=0,*whh1=0,*bih1=0,*bhh1=0,*wcls=0,*bcls=0;
    const int *ctx=0,*pos=0;
    int nwhh = 0, nb = 0;
    for (int i = 0; i < n_in; i++) {
        int s = in_sizes[i]; const void* p = d_in[i];
        switch (s) {
            case 30000000: emb  = (const float*)p; break;
            case 614400:   wih0 = (const float*)p; break;
            case 1048576:  wih1 = (const float*)p; break;
            case 524288:   if (nwhh++ == 0) whh0 = (const float*)p;
                           else             whh1 = (const float*)p; break;
            case 2048:     if (nb == 0) bih0 = (const float*)p;
                           else if (nb == 1) bhh0 = (const float*)p;
                           else if (nb == 2) bih1 = (const float*)p;
                           else              bhh1 = (const float*)p;
                           nb++; break;
            case 1024:     wcls = (const float*)p; break;
            case 2:        bcls = (const float*)p; break;
            case 32768:    ctx  = (const int*)p; break;
            case 64:       pos  = (const int*)p; break;
            default: break;
        }
    }

    cudaFuncSetAttribute(hmma_gemm, cudaFuncAttributeMaxDynamicSharedMemorySize, GEMM_SMEM);
    cudaFuncSetAttribute(lstm_rec,  cudaFuncAttributeMaxDynamicSharedMemorySize, LSTM_SMEM);

    dim3 ggrid(16, 256);
    // layer 0 (+ hoist independent conv_w for layer 1)
    conv_a<<<NROWS, 128>>>(emb, ctx);
    conv_w<<<GCOLS, 128>>>(wih0, 0);
    hmma_gemm<<<ggrid, 256, GEMM_SMEM>>>(bih0, bhh0, 960);
    conv_w<<<GCOLS, 128>>>(wih1, 1);              // independent of lstm L0
    lstm_rec<<<64, 256, LSTM_SMEM>>>(whh0, 0);    // both dirs; writes d_A2
    // layer 1
    hmma_gemm<<<ggrid, 256, GEMM_SMEM>>>(bih1, bhh1, 1536);
    lstm_rec<<<64, 256, LSTM_SMEM>>>(whh1, 1);    // both dirs; writes d_Y1
    // classifier
    epilogue<<<64, 512>>>(pos, wcls, bcls, (float*)d_out);
}

// round 17
// speedup vs baseline: 1.8679x; 1.1667x over previous
#include <cuda_runtime.h>
#include <cuda_bf16.h>
#include <math.h>
#include <stdint.h>

#define VOCAB 100000
#define EMB   300
#define HID   256
#define BATCH 64
#define SEQ   512
#define NROWS (SEQ*BATCH)   /* 32768 */
#define GCOLS 2048          /* 2 dirs * 4 gates * 256 */
#define K3MAX 1536          /* max concatenated K (layer 1: 3*512) */

// ---------------- static scratch (no allocations allowed) -------------------
__device__ float d_G [(size_t)NROWS * GCOLS];     // gate preactivations
__device__ float d_Y1[(size_t)NROWS * 512];       // layer-1 output (t,b,2H)
__device__ __nv_bfloat16 d_A2[(size_t)NROWS * K3MAX];  // [Ahi|Alo|Ahi]
__device__ __nv_bfloat16 d_W2[(size_t)GCOLS * K3MAX];  // [Whi|Whi|Wlo]

__device__ __forceinline__ float fsigm(float x) {
    return __fdividef(1.f, 1.f + __expf(-x));
}
__device__ __forceinline__ float ftanh(float x) {
    return __fdividef(2.f, 1.f + __expf(-2.f * x)) - 1.f;
}

// ---------------- MMA helpers -----------------------------------------------
__device__ __forceinline__ void ldsm_x4(uint32_t& r0, uint32_t& r1,
                                        uint32_t& r2, uint32_t& r3, uint32_t a) {
    asm volatile("ldmatrix.sync.aligned.m8n8.x4.shared.b16 {%0,%1,%2,%3}, [%4];"
                 : "=r"(r0), "=r"(r1), "=r"(r2), "=r"(r3) : "r"(a));
}
__device__ __forceinline__ void ldsm_x2(uint32_t& r0, uint32_t& r1, uint32_t a) {
    asm volatile("ldmatrix.sync.aligned.m8n8.x2.shared.b16 {%0,%1}, [%2];"
                 : "=r"(r0), "=r"(r1) : "r"(a));
}
__device__ __forceinline__ void mma16816(float* d, const uint32_t* a, const uint32_t* b) {
    asm volatile("mma.sync.aligned.m16n8k16.row.col.f32.bf16.bf16.f32 "
                 "{%0,%1,%2,%3}, {%4,%5,%6,%7}, {%8,%9}, {%0,%1,%2,%3};"
                 : "+f"(d[0]), "+f"(d[1]), "+f"(d[2]), "+f"(d[3])
                 : "r"(a[0]), "r"(a[1]), "r"(a[2]), "r"(a[3]), "r"(b[0]), "r"(b[1]));
}

// ============================================================================
// conv_a / conv_w (frozen)
// ============================================================================
__global__ void conv_a(const float* __restrict__ emb, const int* __restrict__ tokens)
{
    int r = blockIdx.x;
    int b = r & 63, t = r >> 6;
    const float* src = emb + (size_t)tokens[b * SEQ + t] * EMB;
    __nv_bfloat16* row = d_A2 + (size_t)r * 960;
    for (int c = threadIdx.x; c < 320; c += blockDim.x) {
        float x = (c < EMB) ? src[c] : 0.f;
        __nv_bfloat16 h = __float2bfloat16(x);
        row[c]       = h;
        row[320 + c] = __float2bfloat16(x - __bfloat162float(h));
        row[640 + c] = h;
    }
}

__global__ void conv_w(const float* __restrict__ w, int layer)
{
    int r = blockIdx.x;
    int K, Kp, stride;
    if (layer == 0) { K = 300; Kp = 320; stride = 960; }
    else            { K = 512; Kp = 512; stride = 1536; }
    const float* src = w + (size_t)r * K;
    __nv_bfloat16* row = d_W2 + (size_t)r * stride;
    for (int c = threadIdx.x; c < Kp; c += blockDim.x) {
        float x = (c < K) ? src[c] : 0.f;
        __nv_bfloat16 h = __float2bfloat16(x);
        row[c]        = h;
        row[Kp + c]   = h;
        row[2*Kp + c] = __float2bfloat16(x - __bfloat162float(h));
    }
}

// ============================================================================
// HMMA GEMM with 3-stage cp.async pipeline (frozen).
// ============================================================================
#define SROW 40
#define STG_B (128 * SROW * 2)
#define B_OFF (3 * STG_B)
#define BSUM_OFF (6 * STG_B)
#define GEMM_SMEM (BSUM_OFF + 512)

__device__ __forceinline__ void cpasync16(uint32_t saddr, const void* gaddr) {
    asm volatile("cp.async.cg.shared.global [%0], [%1], 16;" :: "r"(saddr), "l"(gaddr));
}
#define CP_COMMIT() asm volatile("cp.async.commit_group;" ::: "memory")
#define CP_WAIT1()  asm volatile("cp.async.wait_group 1;" ::: "memory")

__global__ void __launch_bounds__(256)
hmma_gemm(const float* __restrict__ b1, const float* __restrict__ b2, int Kp3)
{
    extern __shared__ __align__(16) char smem[];
    uint32_t sbase = (uint32_t)__cvta_generic_to_shared(smem);
    float* bsum = (float*)(smem + BSUM_OFF);

    const int tid = threadIdx.x, lane = tid & 31, w = tid >> 5;
    const int bn = blockIdx.x, bm = blockIdx.y;
    const int wm = (w & 1) * 64, wn = (w >> 1) * 32;

    if (tid < 128) { int c = bn * 128 + tid; bsum[tid] = b1[c] + b2[c]; }

    const __nv_bfloat16* gA = d_A2 + (size_t)(bm * 128) * Kp3;
    const __nv_bfloat16* gB = d_W2 + (size_t)(bn * 128) * Kp3;

    const int ar0 = tid >> 2,          ac0 = (tid & 3) * 8;
    const int ar1 = (tid + 256) >> 2,  ac1 = (tid & 3) * 8;

    float acc[4][4][4];
#pragma unroll
    for (int m = 0; m < 4; m++)
#pragma unroll
        for (int n = 0; n < 4; n++)
#pragma unroll
            for (int q = 0; q < 4; q++) acc[m][n][q] = 0.f;

    const int nk = Kp3 / 32;

    auto issue = [&](int s, int kb) {
        uint32_t sa = sbase + s * STG_B;
        uint32_t sb = sbase + B_OFF + s * STG_B;
        cpasync16(sa + (ar0 * SROW + ac0) * 2, gA + (size_t)ar0 * Kp3 + kb + ac0);
        cpasync16(sa + (ar1 * SROW + ac1) * 2, gA + (size_t)ar1 * Kp3 + kb + ac1);
        cpasync16(sb + (ar0 * SROW + ac0) * 2, gB + (size_t)ar0 * Kp3 + kb + ac0);
        cpasync16(sb + (ar1 * SROW + ac1) * 2, gB + (size_t)ar1 * Kp3 + kb + ac1);
    };

    issue(0, 0);  CP_COMMIT();
    issue(1, 32); CP_COMMIT();

    int stage = 0;
    for (int kt = 0; kt < nk; kt++) {
        CP_WAIT1();
        __syncthreads();
        if (kt + 2 < nk) issue((stage + 2) % 3, (kt + 2) * 32);
        CP_COMMIT();

        const uint32_t bA = sbase + stage * STG_B;
        const uint32_t bB = sbase + B_OFF + stage * STG_B;
#pragma unroll
        for (int ks = 0; ks < 2; ks++) {
            const int k0 = ks * 16;
            uint32_t a[4][4], bf[4][2];
#pragma unroll
            for (int mt = 0; mt < 4; mt++) {
                uint32_t ad = bA + (((wm + mt*16 + (lane & 15)) * SROW
                                     + k0 + (lane >> 4) * 8) << 1);
                ldsm_x4(a[mt][0], a[mt][1], a[mt][2], a[mt][3], ad);
            }
#pragma unroll
            for (int nt = 0; nt < 4; nt++) {
                uint32_t ad = bB + (((wn + nt*8 + (lane & 7)) * SROW
                                     + k0 + ((lane >> 3) & 1) * 8) << 1);
                ldsm_x2(bf[nt][0], bf[nt][1], ad);
            }
#pragma unroll
            for (int mt = 0; mt < 4; mt++)
#pragma unroll
                for (int nt = 0; nt < 4; nt++)
                    mma16816(acc[mt][nt], a[mt], bf[nt]);
        }
        stage = (stage + 1) % 3;
    }

#pragma unroll
    for (int mt = 0; mt < 4; mt++) {
        int r0 = bm * 128 + wm + mt * 16 + (lane >> 2);
#pragma unroll
        for (int nt = 0; nt < 4; nt++) {
            int c  = wn + nt * 8 + (lane & 3) * 2;
            int cg = bn * 128 + c;
            float2 v0 = make_float2(acc[mt][nt][0] + bsum[c],
                                    acc[mt][nt][1] + bsum[c + 1]);
            float2 v1 = make_float2(acc[mt][nt][2] + bsum[c],
                                    acc[mt][nt][3] + bsum[c + 1]);
            *(float2*)&d_G[(size_t)r0 * GCOLS + cg]       = v0;
            *(float2*)&d_G[(size_t)(r0 + 8) * GCOLS + cg] = v1;
        }
    }
}

// ============================================================================
// LSTM recurrence v8: DIRECTION WARP SPECIALIZATION.
// 8 clusters x 8 CTAs; warps 0-3 = dir0, warps 4-7 = dir1, fully independent
// pipelines (own mbar, own named barrier, own ps region, own elected arrives).
// Superstep = max(dir phases) instead of their sum.
// Per warp: 2 m-tiles (32 gate rows), Whi frags in 128 regs, Wlo via ldsm,
// fused hi/lo h-fragment ldsm_x4. Push exchange (R14 protocol).
// ============================================================================
#define HSTR 264
#define WLO0 0
#define WLO1 67584
#define SCR  135168
#define HBUF 8448                       /* per (dir,par): 2 planes x 8 x 264 x 2B */
#define LOB2 4224                       /* hi->lo plane offset */
#define PS_OFF (SCR + 33792)            /* 168960: ps[2][8][136] f32 */
#define MB_OFF (PS_OFF + 8704)          /* 177664 */
#define LSTM_SMEM (SCR + 67584)         /* 202752 (staging needs SCR+67584) */

__device__ __forceinline__ void mbar_wait_cluster(uint32_t mb, uint32_t parity) {
    uint32_t done;
    asm volatile("{\n\t.reg .pred p;\n\t"
                 "mbarrier.try_wait.parity.acquire.cluster.shared::cta.b64 p, [%1], %2;\n\t"
                 "selp.b32 %0, 1, 0, p;\n\t}"
                 : "=r"(done) : "r"(mb), "r"(parity) : "memory");
    if (!done) {
        asm volatile("{\n\t.reg .pred P1;\n\t"
                     "WL_%=:\n\t"
                     "mbarrier.try_wait.parity.acquire.cluster.shared::cta.b64 P1, [%0], %1, 0x989680;\n\t"
                     "@P1 bra.uni WD_%=;\n\t"
                     "bra.uni WL_%=;\n\t"
                     "WD_%=:\n\t}" :: "r"(mb), "r"(parity) : "memory");
    }
}

__global__ void __cluster_dims__(8,1,1) __launch_bounds__(256,1)
lstm_rec(const float* __restrict__ whh, int layer)
{
    extern __shared__ __align__(16) char ls[];
    uint32_t smb = (uint32_t)__cvta_generic_to_shared(ls);

    const int tid  = threadIdx.x;
    const int lane = tid & 31;
    const int w    = tid >> 5;
    const int d    = w >> 2;            // direction group (0/1)
    const int w2   = w & 3;             // warp within group
    const int hc   = blockIdx.x & 7;    // cluster rank = col stripe
    const int B0   = (blockIdx.x >> 3) * 8;
    const int barid = d + 1;            // named barrier per group

    float* psd = (float*)(ls + PS_OFF) + d * 1088;   // ps[8][136] per dir

    // ---- prologue: stage Whi per dir into SCR; preload own dir's frags ----
    uint32_t wh[2][16][4];              // [m-tile][ks][frag]
#pragma unroll
    for (int dd = 0; dd < 2; dd++) {
        __nv_bfloat16* WhiT = (__nv_bfloat16*)(ls + SCR);
        __nv_bfloat16* WloR = (__nv_bfloat16*)(ls + (dd ? WLO1 : WLO0));
        for (int idx = tid; idx < 128 * 256; idx += 256) {
            int r = idx >> 8, k = idx & 255;
            float x = whh[((size_t)dd*1024 + (r>>5)*256 + hc*32 + (r&31)) * 256 + k];
            __nv_bfloat16 hi = __float2bfloat16(x);
            WhiT[r*HSTR + k] = hi;
            WloR[r*HSTR + k] = __float2bfloat16(x - __bfloat162float(hi));
        }
        __syncthreads();
        if (dd == d) {
#pragma unroll
            for (int tile = 0; tile < 2; tile++)
#pragma unroll
                for (int ks = 0; ks < 16; ks++) {
                    uint32_t ao = (((w2*32 + tile*16 + (lane & 15)) * HSTR
                                    + ks*16 + (lane >> 4)*8) << 1);
                    ldsm_x4(wh[tile][ks][0], wh[tile][ks][1],
                            wh[tile][ks][2], wh[tile][ks][3], smb + SCR + ao);
                }
        }
        __syncthreads();
    }

    // ---- zero Hd, init mbars (count 8x256=2048 per dir) ----
    for (int i = tid; i < 33792/4; i += 256) ((uint32_t*)(ls + SCR))[i] = 0u;
    if (tid == 0) {
        asm volatile("mbarrier.init.shared.b64 [%0], %1;" :: "r"(smb + MB_OFF),     "r"(2048u) : "memory");
        asm volatile("mbarrier.init.shared.b64 [%0], %1;" :: "r"(smb + MB_OFF + 8), "r"(2048u) : "memory");
    }
    __syncthreads();
    asm volatile("barrier.cluster.arrive.aligned;" ::: "memory");
    asm volatile("barrier.cluster.wait.aligned;"   ::: "memory");

    // push addresses: own slot (batch w2) in each peer CTA; batch w2+4 = +2112B
    uint32_t pa[8];
    {
        uint32_t own = smb + SCR + (uint32_t)((w2*HSTR + hc*32 + lane) << 1);
#pragma unroll
        for (unsigned r = 0; r < 8; r++)
            asm volatile("mapa.shared::cluster.u32 %0, %1, %2;"
                         : "=r"(pa[r]) : "r"(own), "r"(r));
    }
    const uint32_t mbme = smb + MB_OFF + d*8;
    uint32_t mbmap = 0;                 // elected arrive target (rank = lane)
    if (w2 == 0 && lane < 8)
        asm volatile("mapa.shared::cluster.u32 %0, %1, %2;"
                     : "=r"(mbmap) : "r"(mbme), "r"(lane));

    float creg[2] = {0.f, 0.f};         // c-state for batches w2 and w2+4

    for (int t = 0; t < SEQ; t++) {
        const int par = t & 1;
        // prefetch gate preactivations for both batch slots (own dir)
        float gp0[4], gp1[4];
        {
            size_t rb0 = ((size_t)t*64 + B0 + w2) * GCOLS + (size_t)d*1024 + hc*32 + lane;
            size_t rb1 = rb0 + 4 * GCOLS;
#pragma unroll
            for (int g = 0; g < 4; g++) { gp0[g] = d_G[rb0 + g*256]; gp1[g] = d_G[rb1 + g*256]; }
        }

        if (t > 0) mbar_wait_cluster(mbme, (uint32_t)((t + 1) & 1));

        // ---- tensor dot: 2 m-tiles, 3-term split product ----
        float acc[2][2][4];
#pragma unroll
        for (int q = 0; q < 4; q++) {
            acc[0][0][q] = acc[0][1][q] = 0.f;
            acc[1][0][q] = acc[1][1][q] = 0.f;
        }
        const uint32_t Hp = smb + SCR + (uint32_t)((d*2 + par) * HBUF);
        const uint32_t hb = Hp
            + (uint32_t)((((lane >> 4) & 1) * LOB2)
            + ((((lane & 7) * HSTR) + (((lane >> 3) & 1) * 8)) << 1));
        const uint32_t wlo = smb + (d ? WLO1 : WLO0);
#pragma unroll
        for (int ks = 0; ks < 16; ks++) {
            uint32_t hf[4];
            ldsm_x4(hf[0], hf[1], hf[2], hf[3], hb + (uint32_t)(ks * 32));
#pragma unroll
            for (int tile = 0; tile < 2; tile++) {
                uint32_t wl[4];
                uint32_t ao = (((w2*32 + tile*16 + (lane & 15)) * HSTR
                                + ks*16 + (lane >> 4)*8) << 1);
                ldsm_x4(wl[0], wl[1], wl[2], wl[3], wlo + ao);
                mma16816(acc[tile][ks & 1], wh[tile][ks], hf);      // Whi.hhi
                mma16816(acc[tile][ks & 1], wh[tile][ks], hf + 2);  // Whi.hlo
                mma16816(acc[tile][ks & 1], wl, hf);                // Wlo.hhi
            }
        }
        // ---- transpose through psd ----
#pragma unroll
        for (int tile = 0; tile < 2; tile++) {
            int gr = w2*32 + tile*16 + (lane >> 2);
            int c0 = (lane & 3) * 2;
            float v0 = acc[tile][0][0] + acc[tile][1][0];
            float v1 = acc[tile][0][1] + acc[tile][1][1];
            float v2 = acc[tile][0][2] + acc[tile][1][2];
            float v3 = acc[tile][0][3] + acc[tile][1][3];
            psd[c0*136 + gr]         = v0;
            psd[(c0+1)*136 + gr]     = v1;
            psd[c0*136 + gr + 8]     = v2;
            psd[(c0+1)*136 + gr + 8] = v3;
        }
        asm volatile("bar.sync %0, 128;" :: "r"(barid) : "memory");

        // ---- cell update + push: 2 batch slots ----
        uint32_t off = (uint32_t)((d*2 + (par^1)) * HBUF);
#pragma unroll
        for (int s = 0; s < 2; s++) {
            int b = w2 + s*4;
            const float* gp = s ? gp1 : gp0;
            float si = psd[b*136 + lane]      + gp[0];
            float sf = psd[b*136 + 32 + lane] + gp[1];
            float sg = psd[b*136 + 64 + lane] + gp[2];
            float so = psd[b*136 + 96 + lane] + gp[3];
            float iv = fsigm(si);
            float fv = fsigm(sf);
            float ov = fsigm(so);
            creg[s] = fv * creg[s] + iv * ftanh(sg);
            float hnew = ov * ftanh(creg[s]);

            __nv_bfloat16 hh = __float2bfloat16(hnew);
            __nv_bfloat16 hl = __float2bfloat16(hnew - __bfloat162float(hh));
            unsigned short hb16 = __bfloat16_as_ushort(hh);
            unsigned short lb16 = __bfloat16_as_ushort(hl);

            uint32_t soff = off + (uint32_t)(s * 4 * HSTR * 2);
#pragma unroll
            for (unsigned r = 0; r < 8; r++) {
                asm volatile("st.shared::cluster.u16 [%0], %1;"
                             :: "r"(pa[r] + soff), "h"(hb16) : "memory");
                asm volatile("st.shared::cluster.u16 [%0], %1;"
                             :: "r"(pa[r] + soff + LOB2), "h"(lb16) : "memory");
            }

            // global h store
            int col = d*256 + hc*32 + lane;
            size_t orow = (size_t)t*64 + B0 + b;
            if (layer == 0) {
                __nv_bfloat16* arow = d_A2 + orow * 1536;
                arow[col]        = hh;
                arow[512 + col]  = hl;
                arow[1024 + col] = hh;
            } else {
                d_Y1[orow * 512 + col] = hnew;
            }
        }
        asm volatile("bar.sync %0, 128;" :: "r"(barid) : "memory");

        // ---- elected remote arrives (8 threads x count 256) ----
        if (w2 == 0 && lane < 8)
            asm volatile("mbarrier.arrive.release.cluster.shared::cluster.b64 _, [%0], %1;"
                         :: "r"(mbmap), "r"(256u) : "memory");
    }

    asm volatile("barrier.cluster.arrive.aligned;" ::: "memory");
    asm volatile("barrier.cluster.wait.aligned;"   ::: "memory");
}

// ============================================================================
// Epilogue (frozen)
// ============================================================================
__global__ void __launch_bounds__(512)
epilogue(const int* __restrict__ pos, const float* __restrict__ wcls,
         const float* __restrict__ bcls, float* __restrict__ out)
{
    __shared__ float s0[512], s1[512];
    int b = blockIdx.x, i = threadIdx.x;
    int t = pos[b];
    float y = d_Y1[((size_t)t*64 + b) * 512 + i];
    out[256 + b*512 + i] = y;
    s0[i] = y * wcls[i];
    s1[i] = y * wcls[512 + i];
    __syncthreads();
    for (int st = 256; st > 0; st >>= 1) {
        if (i < st) { s0[i] += s0[i+st]; s1[i] += s1[i+st]; }
        __syncthreads();
    }
    if (i == 0) {
        float l0 = s0[0] + bcls[0], l1 = s1[0] + bcls[1];
        out[b*2+0] = l0;            out[b*2+1] = l1;
        out[128 + b*2+0] = 1.f/(1.f+expf(-l0));
        out[128 + b*2+1] = 1.f/(1.f+expf(-l1));
    }
}

// ============================================================================
extern "C" void kernel_launch(void* const* d_in, const int* in_sizes, int n_in,
                              void* d_out, int out_size)
{
    const float *emb=0,*wih0=0,*whh0=0,*bih0=0,*bhh0=0;
    const float *wih1=0,*whh1=0,*bih1=0,*bhh1=0,*wcls=0,*bcls=0;
    const int *ctx=0,*pos=0;
    int nwhh = 0, nb = 0;
    for (int i = 0; i < n_in; i++) {
        int s = in_sizes[i]; const void* p = d_in[i];
        switch (s) {
            case 30000000: emb  = (const float*)p; break;
            case 614400:   wih0 = (const float*)p; break;
            case 1048576:  wih1 = (const float*)p; break;
            case 524288:   if (nwhh++ == 0) whh0 = (const float*)p;
                           else             whh1 = (const float*)p; break;
            case 2048:     if (nb == 0) bih0 = (const float*)p;
                           else if (nb == 1) bhh0 = (const float*)p;
                           else if (nb == 2) bih1 = (const float*)p;
                           else              bhh1 = (const float*)p;
                           nb++; break;
            case 1024:     wcls = (const float*)p; break;
            case 2:        bcls = (const float*)p; break;
            case 32768:    ctx  = (const int*)p; break;
            case 64:       pos  = (const int*)p; break;
            default: break;
        }
    }

    cudaFuncSetAttribute(hmma_gemm, cudaFuncAttributeMaxDynamicSharedMemorySize, GEMM_SMEM);
    cudaFuncSetAttribute(lstm_rec,  cudaFuncAttributeMaxDynamicSharedMemorySize, LSTM_SMEM);

    dim3 ggrid(16, 256);
    // layer 0 (+ hoist independent conv_w for layer 1)
    conv_a<<<NROWS, 128>>>(emb, ctx);
    conv_w<<<GCOLS, 128>>>(wih0, 0);
    hmma_gemm<<<ggrid, 256, GEMM_SMEM>>>(bih0, bhh0, 960);
    conv_w<<<GCOLS, 128>>>(wih1, 1);              // independent of lstm L0
    lstm_rec<<<64, 256, LSTM_SMEM>>>(whh0, 0);    // both dirs; writes d_A2
    // layer 1
    hmma_gemm<<<ggrid, 256, GEMM_SMEM>>>(bih1, bhh1, 1536);
    lstm_rec<<<64, 256, LSTM_SMEM>>>(whh1, 1);    // both dirs; writes d_Y1
    // classifier
    epilogue<<<64, 512>>>(pos, wcls, bcls, (float*)d_out);
}